// round 13
// baseline (speedup 1.0000x reference)
#include <cuda_runtime.h>

// ---------------------------------------------------------------------------
// GCN ensemble on GB300.
// Restructure: gcn(x,W) = A_hat(xW) + b = (A_hat x)W + b  (linearity),
// so every edge aggregation runs at C=128 (cheap side):
//   z1 = A1 x        z2 = A2 x              (agg on input, C=128)
//   t1 = relu(z1 W0 + b0), t2 = relu(z2 W1 + b1)
//   g1 = t1 W2,      g2 = t2 W3             (GEMM first, C=128 out)
//   acc = A1 g1 + A2 g2 + b2 + b3           (agg on output, C=128)
//   out = acc                               (plain-store copy)
// A_hat includes the self-loop term dinv[i]^2 (fused into init/epilogue).
//
// R12 root cause: edge_index is int32 (JAX x64 disabled coerces the
// requested int64), I decoded it as int64 -> garbage indices -> wild
// addresses (R4/R6 "address space" trap + R12 illegal access). Fix:
// device-side dtype detection (k_detect) + dtype-adaptive decode + clamp.
// ---------------------------------------------------------------------------

#define N_MAX 50000
#define E_MAX 800000

// Scratch: static __device__ globals (no runtime allocation allowed).
__device__ int   g_mode;             // 1 = edge buffer is int64, 0 = int32
__device__ int   g_deg1[N_MAX];
__device__ int   g_deg2[N_MAX];
__device__ float g_dinv1[N_MAX];
__device__ float g_dinv2[N_MAX];
__device__ int   g_es1[E_MAX];
__device__ int   g_ed1[E_MAX];
__device__ int   g_es2[E_MAX];
__device__ int   g_ed2[E_MAX];
__device__ float g_w1[E_MAX];
__device__ float g_w2[E_MAX];
__device__ float g_z1[(size_t)N_MAX * 128];
__device__ float g_z2[(size_t)N_MAX * 128];
__device__ float g_t1[(size_t)N_MAX * 256];
__device__ float g_t2[(size_t)N_MAX * 256];
__device__ float g_gg1[(size_t)N_MAX * 128];
__device__ float g_gg2[(size_t)N_MAX * 128];
__device__ float g_out[(size_t)N_MAX * 128];   // atomic-safe output accumulator

// ------------------------------- prep kernels ------------------------------

// Decide edge dtype: sample first <=1024 values as int64; int32 pairs
// re-read as int64 are >= 2^32 whenever the adjacent value != 0, so any
// out-of-range sample means the buffer is int32.
__global__ void k_detect(const void* __restrict__ ei, int E, int N) {
    if (blockIdx.x == 0 && threadIdx.x == 0) {
        const long long* p = (const long long*)ei;
        int m = E < 1024 ? E : 1024;
        int ok = 1;
        for (int i = 0; i < m; i++) {
            long long v = p[i];
            if (v < 0 || v >= (long long)N) { ok = 0; break; }
        }
        g_mode = ok;
    }
}

__global__ void k_zero_deg(int* __restrict__ d1, int* __restrict__ d2, int n) {
    int i = blockIdx.x * blockDim.x + threadIdx.x;
    if (i < n) { d1[i] = 0; d2[i] = 0; }
}

// dtype-adaptive edge decode + clamp + in-degree count (one pass).
__global__ void k_prep_edges(const void* __restrict__ ei,
                             int* __restrict__ es, int* __restrict__ ed,
                             int* __restrict__ deg, int E, int N) {
    int e = blockIdx.x * blockDim.x + threadIdx.x;
    if (e >= E) return;
    int s, d;
    if (g_mode) {
        const long long* p = (const long long*)ei;
        s = (int)p[e];
        d = (int)p[(size_t)E + e];
    } else {
        const int* p = (const int*)ei;
        s = p[e];
        d = p[(size_t)E + e];
    }
    if ((unsigned)s >= (unsigned)N) s = 0;   // defensive: crash -> rel_err
    if ((unsigned)d >= (unsigned)N) d = 0;
    es[e] = s;
    ed[e] = d;
    atomicAdd(&deg[d], 1);
}

__global__ void k_dinv(const int* __restrict__ d1, const int* __restrict__ d2,
                       float* __restrict__ v1, float* __restrict__ v2, int n) {
    int i = blockIdx.x * blockDim.x + threadIdx.x;
    if (i < n) {
        v1[i] = rsqrtf((float)d1[i] + 1.0f);
        v2[i] = rsqrtf((float)d2[i] + 1.0f);
    }
}

__global__ void k_edgew(const int* __restrict__ es, const int* __restrict__ ed,
                        const float* __restrict__ dinv, float* __restrict__ w, int E) {
    int e = blockIdx.x * blockDim.x + threadIdx.x;
    if (e < E) w[e] = __ldg(dinv + es[e]) * __ldg(dinv + ed[e]);
}

// z[i][:] = x[i][:] * dinv[i]^2   (self-loop term; agg atomics add on top)
__global__ void k_selfinit(const float* __restrict__ x, const float* __restrict__ dinv,
                           float* __restrict__ z, int n) {
    int t = blockIdx.x * blockDim.x + threadIdx.x;
    int i = t >> 5;
    int c = (t & 31) << 2;
    if (i >= n) return;
    float s = dinv[i];
    s *= s;
    float4 v = *(const float4*)(x + (size_t)i * 128 + c);
    v.x *= s; v.y *= s; v.z *= s; v.w *= s;
    *(float4*)(z + (size_t)i * 128 + c) = v;
}

// ------------------------------- aggregation -------------------------------
// One warp per edge; lane l handles floats [4l, 4l+4) of the 128-wide row.
// Coalesced 512B gather of h[src]; scalar atomicAdd (-> REDG.F32, no return)
// into out[dst]; out is always a __device__ symbol.
__global__ void k_agg(const float* __restrict__ h,
                      const int* __restrict__ es, const int* __restrict__ ed,
                      const float* __restrict__ w,
                      float* __restrict__ out, int E) {
    int t = blockIdx.x * blockDim.x + threadIdx.x;
    int e = t >> 5;
    int lane = t & 31;
    if (e >= E) return;
    int s = __ldg(es + e);
    int d = __ldg(ed + e);
    float ww = __ldg(w + e);
    float4 v = *(const float4*)(h + (size_t)s * 128 + (lane << 2));
    float* p = out + (size_t)d * 128 + (lane << 2);
    atomicAdd(p + 0, v.x * ww);
    atomicAdd(p + 1, v.y * ww);
    atomicAdd(p + 2, v.z * ww);
    atomicAdd(p + 3, v.w * ww);
}

// Final copy: d_out = acc (plain vectorized stores; no atomics touch d_out).
__global__ void k_copy(const float* __restrict__ src, float* __restrict__ dst,
                       size_t n4) {
    size_t i = (size_t)blockIdx.x * blockDim.x + threadIdx.x;
    if (i < n4) ((float4*)dst)[i] = ((const float4*)src)[i];
}

// --------------------------------- SGEMM -----------------------------------
// C[N,M] = A[N,K] @ W[K,M] (+ fused epilogue). BM=BN=128, BK=16, 256 thr, 8x8.
// MODE 0: C   = relu(acc + bias)
// MODE 1: C2  = acc;  C  = acc*dinv[row]^2 + bias + bias2     (out init)
// MODE 2: C2  = acc;  C += acc*dinv[row]^2                    (out accumulate)
template<int MODE>
__global__ void __launch_bounds__(256)
k_gemm(const float* __restrict__ A, const float* __restrict__ W,
       const float* __restrict__ bias, const float* __restrict__ bias2,
       const float* __restrict__ dinv,
       float* __restrict__ C, float* __restrict__ C2,
       int N, int K, int M) {
    __shared__ float As[16][132];   // transposed A tile, padded (STS conflicts)
    __shared__ float Bs[16][132];   // pad keeps 16B alignment (132*4 % 16 == 0)

    const int bm = blockIdx.x * 128;
    const int bn = blockIdx.y * 128;
    const int tid = threadIdx.x;
    const int tx = tid & 15;        // 16 cols of threads
    const int ty = tid >> 4;        // 16 rows of threads
    const int aRow = tid >> 2;            // 0..63
    const int aCol = (tid & 3) << 2;      // 0,4,8,12
    const int bRow = tid >> 5;            // 0..7
    const int bCol = (tid & 31) << 2;     // 0..124

    float acc[8][8];
#pragma unroll
    for (int i = 0; i < 8; i++)
#pragma unroll
        for (int j = 0; j < 8; j++) acc[i][j] = 0.0f;

    for (int kk = 0; kk < K; kk += 16) {
#pragma unroll
        for (int i = 0; i < 2; i++) {
            int r = bm + aRow + i * 64;
            float4 v = make_float4(0.f, 0.f, 0.f, 0.f);
            if (r < N) v = *(const float4*)(A + (size_t)r * K + kk + aCol);
            As[aCol + 0][aRow + i * 64] = v.x;
            As[aCol + 1][aRow + i * 64] = v.y;
            As[aCol + 2][aRow + i * 64] = v.z;
            As[aCol + 3][aRow + i * 64] = v.w;
        }
#pragma unroll
        for (int i = 0; i < 2; i++) {
            int r = kk + bRow + i * 8;
            *(float4*)&Bs[bRow + i * 8][bCol] =
                *(const float4*)(W + (size_t)r * M + bn + bCol);
        }
        __syncthreads();
#pragma unroll
        for (int k = 0; k < 16; k++) {
            float a[8], b[8];
            *(float4*)(a)     = *(const float4*)&As[k][ty * 8];
            *(float4*)(a + 4) = *(const float4*)&As[k][ty * 8 + 4];
            *(float4*)(b)     = *(const float4*)&Bs[k][tx * 8];
            *(float4*)(b + 4) = *(const float4*)&Bs[k][tx * 8 + 4];
#pragma unroll
            for (int i = 0; i < 8; i++)
#pragma unroll
                for (int j = 0; j < 8; j++)
                    acc[i][j] += a[i] * b[j];
        }
        __syncthreads();
    }

    // epilogue
    float bb[8];
    if (MODE == 0 || MODE == 1) {
#pragma unroll
        for (int j = 0; j < 8; j++) {
            bb[j] = bias[bn + tx * 8 + j];
            if (MODE == 1) bb[j] += bias2[bn + tx * 8 + j];
        }
    }
#pragma unroll
    for (int i = 0; i < 8; i++) {
        int row = bm + ty * 8 + i;
        if (row < N) {
            size_t off = (size_t)row * M + bn + tx * 8;
            if (MODE == 0) {
                float4 o0, o1;
                o0.x = fmaxf(acc[i][0] + bb[0], 0.f);
                o0.y = fmaxf(acc[i][1] + bb[1], 0.f);
                o0.z = fmaxf(acc[i][2] + bb[2], 0.f);
                o0.w = fmaxf(acc[i][3] + bb[3], 0.f);
                o1.x = fmaxf(acc[i][4] + bb[4], 0.f);
                o1.y = fmaxf(acc[i][5] + bb[5], 0.f);
                o1.z = fmaxf(acc[i][6] + bb[6], 0.f);
                o1.w = fmaxf(acc[i][7] + bb[7], 0.f);
                *(float4*)(C + off)     = o0;
                *(float4*)(C + off + 4) = o1;
            } else {
                // raw pre-aggregation matrix g for the edge-scatter pass
                float4 r0 = make_float4(acc[i][0], acc[i][1], acc[i][2], acc[i][3]);
                float4 r1 = make_float4(acc[i][4], acc[i][5], acc[i][6], acc[i][7]);
                *(float4*)(C2 + off)     = r0;
                *(float4*)(C2 + off + 4) = r1;
                float s = dinv[row];
                s *= s;
                float4 o0, o1;
                if (MODE == 1) {
                    o0.x = r0.x * s + bb[0]; o0.y = r0.y * s + bb[1];
                    o0.z = r0.z * s + bb[2]; o0.w = r0.w * s + bb[3];
                    o1.x = r1.x * s + bb[4]; o1.y = r1.y * s + bb[5];
                    o1.z = r1.z * s + bb[6]; o1.w = r1.w * s + bb[7];
                } else {
                    float4 c0 = *(const float4*)(C + off);
                    float4 c1 = *(const float4*)(C + off + 4);
                    o0.x = c0.x + r0.x * s; o0.y = c0.y + r0.y * s;
                    o0.z = c0.z + r0.z * s; o0.w = c0.w + r0.w * s;
                    o1.x = c1.x + r1.x * s; o1.y = c1.y + r1.y * s;
                    o1.z = c1.z + r1.z * s; o1.w = c1.w + r1.w * s;
                }
                *(float4*)(C + off)     = o0;
                *(float4*)(C + off + 4) = o1;
            }
        }
    }
}

// --------------------------------- launch ----------------------------------

extern "C" void kernel_launch(void* const* d_in, const int* in_sizes, int n_in,
                              void* d_out, int out_size) {
    const float* x   = (const float*)d_in[0];
    const void*  ei1 = d_in[1];
    const void*  ei2 = d_in[2];
    const float* W0 = (const float*)d_in[3];
    const float* b0 = (const float*)d_in[4];
    const float* W1 = (const float*)d_in[5];
    const float* b1 = (const float*)d_in[6];
    const float* W2 = (const float*)d_in[7];
    const float* b2 = (const float*)d_in[8];
    const float* W3 = (const float*)d_in[9];
    const float* b3 = (const float*)d_in[10];
    float* out = (float*)d_out;

    int N = in_sizes[0] / 128;
    int E = in_sizes[1] / 2;
    if (N > N_MAX) N = N_MAX;
    if (E > E_MAX) E = E_MAX;

    int *deg1, *deg2, *es1, *ed1, *es2, *ed2;
    float *dinv1, *dinv2, *w1, *w2, *z1, *z2, *t1, *t2, *gg1, *gg2, *acc;
    cudaGetSymbolAddress((void**)&deg1,  g_deg1);
    cudaGetSymbolAddress((void**)&deg2,  g_deg2);
    cudaGetSymbolAddress((void**)&dinv1, g_dinv1);
    cudaGetSymbolAddress((void**)&dinv2, g_dinv2);
    cudaGetSymbolAddress((void**)&es1,   g_es1);
    cudaGetSymbolAddress((void**)&ed1,   g_ed1);
    cudaGetSymbolAddress((void**)&es2,   g_es2);
    cudaGetSymbolAddress((void**)&ed2,   g_ed2);
    cudaGetSymbolAddress((void**)&w1,    g_w1);
    cudaGetSymbolAddress((void**)&w2,    g_w2);
    cudaGetSymbolAddress((void**)&z1,    g_z1);
    cudaGetSymbolAddress((void**)&z2,    g_z2);
    cudaGetSymbolAddress((void**)&t1,    g_t1);
    cudaGetSymbolAddress((void**)&t2,    g_t2);
    cudaGetSymbolAddress((void**)&gg1,   g_gg1);
    cudaGetSymbolAddress((void**)&gg2,   g_gg2);
    cudaGetSymbolAddress((void**)&acc,   g_out);

    const int T = 256;
    int gN  = (N + T - 1) / T;
    int gE  = (E + T - 1) / T;
    int gNC = ((N * 32) + T - 1) / T;          // N rows x 32 float4 lanes
    long long ethreads = (long long)E * 32;
    int gEC = (int)((ethreads + T - 1) / T);   // E warps

    // edge dtype detection + degrees + decode + per-edge norm weights
    k_detect<<<1, 32>>>(ei1, E, N);
    k_zero_deg<<<gN, T>>>(deg1, deg2, N);
    k_prep_edges<<<gE, T>>>(ei1, es1, ed1, deg1, E, N);
    k_prep_edges<<<gE, T>>>(ei2, es2, ed2, deg2, E, N);
    k_dinv<<<gN, T>>>(deg1, deg2, dinv1, dinv2, N);
    k_edgew<<<gE, T>>>(es1, ed1, dinv1, w1, E);
    k_edgew<<<gE, T>>>(es2, ed2, dinv2, w2, E);

    // z = A_hat x  (self-loop init, then edge scatter into device scratch)
    k_selfinit<<<gNC, T>>>(x, dinv1, z1, N);
    k_selfinit<<<gNC, T>>>(x, dinv2, z2, N);
    k_agg<<<gEC, T>>>(x, es1, ed1, w1, z1, E);
    k_agg<<<gEC, T>>>(x, es2, ed2, w2, z2, E);

    // t = relu(z W + b)
    dim3 grid1((N + 127) / 128, 256 / 128);
    k_gemm<0><<<grid1, 256>>>(z1, W0, b0, nullptr, nullptr, t1, nullptr, N, 128, 256);
    k_gemm<0><<<grid1, 256>>>(z2, W1, b1, nullptr, nullptr, t2, nullptr, N, 128, 256);

    // g = t W;  acc seeded with self-loop terms + (b2 + b3)
    dim3 grid2((N + 127) / 128, 1);
    k_gemm<1><<<grid2, 256>>>(t1, W2, b2, b3, dinv1, acc, gg1, N, 256, 128);
    k_gemm<2><<<grid2, 256>>>(t2, W3, nullptr, nullptr, dinv2, acc, gg2, N, 256, 128);

    // acc += A1 g1 + A2 g2 (edge scatter into device scratch, atomic-safe)
    k_agg<<<gEC, T>>>(gg1, es1, ed1, w1, acc, E);
    k_agg<<<gEC, T>>>(gg2, es2, ed2, w2, acc, E);

    // d_out = acc (plain stores only)
    size_t n4 = (size_t)N * 32;
    k_copy<<<(int)((n4 + T - 1) / T), T>>>(acc, out, n4);
}

// round 15
// speedup vs baseline: 2.0347x; 2.0347x over previous
#include <cuda_runtime.h>

// ---------------------------------------------------------------------------
// GCN ensemble on GB300 — R14.
// Linearity restructure (all aggregations at C=128) + CSR gather (no float
// atomics, plain stores, final gather writes d_out directly) + double-
// buffered SGEMM.
//   z1 = A1 x, z2 = A2 x                      (CSR gather, C=128)
//   t1 = relu(z1 W0 + b0), t2 = relu(z2 W1 + b1)   (GEMM mode0)
//   g1 = t1 W2, g2 = t2 W3                    (GEMM mode3, raw store)
//   out = A1 g1 + A2 g2 + b2 + b3             (CSR gather -> d_out)
// A_hat includes self-loop dinv[i]^2 (folded into the gathers).
// ---------------------------------------------------------------------------

#define N_MAX 50000
#define E_MAX 800000

__device__ int   g_mode;             // 1 = edge buffer is int64, 0 = int32
__device__ int   g_deg1[N_MAX];
__device__ int   g_deg2[N_MAX];
__device__ int   g_cur1[N_MAX];
__device__ int   g_cur2[N_MAX];
__device__ int   g_rp1[N_MAX + 1];
__device__ int   g_rp2[N_MAX + 1];
__device__ float g_dinv1[N_MAX];
__device__ float g_dinv2[N_MAX];
__device__ int   g_es1[E_MAX];
__device__ int   g_ed1[E_MAX];
__device__ int   g_es2[E_MAX];
__device__ int   g_ed2[E_MAX];
__device__ int   g_cs1[E_MAX];       // CSR src, sorted by dst
__device__ int   g_cs2[E_MAX];
__device__ float g_cw1[E_MAX];       // CSR edge weight
__device__ float g_cw2[E_MAX];
__device__ float g_z1[(size_t)N_MAX * 128];
__device__ float g_z2[(size_t)N_MAX * 128];
__device__ float g_t1[(size_t)N_MAX * 256];
__device__ float g_t2[(size_t)N_MAX * 256];
__device__ float g_gg1[(size_t)N_MAX * 128];
__device__ float g_gg2[(size_t)N_MAX * 128];

// ------------------------------- prep kernels ------------------------------

// Edge dtype detection: int32 pairs re-read as int64 land outside [0,N)
// whenever the adjacent word != 0, so 1024 in-range samples => int64.
__global__ void k_detect(const void* __restrict__ ei, int E, int N) {
    if (blockIdx.x == 0 && threadIdx.x == 0) {
        const long long* p = (const long long*)ei;
        int m = E < 1024 ? E : 1024;
        int ok = 1;
        for (int i = 0; i < m; i++) {
            long long v = p[i];
            if (v < 0 || v >= (long long)N) { ok = 0; break; }
        }
        g_mode = ok;
    }
}

__global__ void k_zero4(int* __restrict__ a, int* __restrict__ b,
                        int* __restrict__ c, int* __restrict__ d, int n) {
    int i = blockIdx.x * blockDim.x + threadIdx.x;
    if (i < n) { a[i] = 0; b[i] = 0; c[i] = 0; d[i] = 0; }
}

// dtype-adaptive decode + clamp + in-degree histogram.
__global__ void k_prep_edges(const void* __restrict__ ei,
                             int* __restrict__ es, int* __restrict__ ed,
                             int* __restrict__ deg, int E, int N) {
    int e = blockIdx.x * blockDim.x + threadIdx.x;
    if (e >= E) return;
    int s, d;
    if (g_mode) {
        const long long* p = (const long long*)ei;
        s = (int)p[e];
        d = (int)p[(size_t)E + e];
    } else {
        const int* p = (const int*)ei;
        s = p[e];
        d = p[(size_t)E + e];
    }
    if ((unsigned)s >= (unsigned)N) s = 0;   // defensive
    if ((unsigned)d >= (unsigned)N) d = 0;
    es[e] = s;
    ed[e] = d;
    atomicAdd(&deg[d], 1);
}

__global__ void k_dinv(const int* __restrict__ d1, const int* __restrict__ d2,
                       float* __restrict__ v1, float* __restrict__ v2, int n) {
    int i = blockIdx.x * blockDim.x + threadIdx.x;
    if (i < n) {
        v1[i] = rsqrtf((float)d1[i] + 1.0f);
        v2[i] = rsqrtf((float)d2[i] + 1.0f);
    }
}

// Exclusive scan of deg -> rowptr. One block per array (grid = 2).
__global__ void k_scan(const int* __restrict__ degA, int* __restrict__ rpA,
                       const int* __restrict__ degB, int* __restrict__ rpB,
                       int n) {
    const int* deg = blockIdx.x == 0 ? degA : degB;
    int* rp        = blockIdx.x == 0 ? rpA  : rpB;
    __shared__ int sh[1024];
    __shared__ int carry;
    int tid = threadIdx.x;
    if (tid == 0) { carry = 0; rp[0] = 0; }
    __syncthreads();
    for (int base = 0; base < n; base += 1024) {
        int i = base + tid;
        int v = (i < n) ? deg[i] : 0;
        sh[tid] = v;
        __syncthreads();
#pragma unroll
        for (int off = 1; off < 1024; off <<= 1) {
            int t = (tid >= off) ? sh[tid - off] : 0;
            __syncthreads();
            sh[tid] += t;
            __syncthreads();
        }
        if (i < n) rp[i + 1] = carry + sh[tid];   // inclusive + carry = excl[i+1]
        __syncthreads();
        if (tid == 0) carry += sh[1023];
        __syncthreads();
    }
}

// Counting-sort edges into CSR; fuse edge-weight computation.
__global__ void k_scatter(const int* __restrict__ es, const int* __restrict__ ed,
                          const float* __restrict__ dinv,
                          const int* __restrict__ rp, int* __restrict__ cur,
                          int* __restrict__ cs, float* __restrict__ cw, int E) {
    int e = blockIdx.x * blockDim.x + threadIdx.x;
    if (e >= E) return;
    int s = es[e], d = ed[e];
    int pos = rp[d] + atomicAdd(&cur[d], 1);
    cs[pos] = s;
    cw[pos] = __ldg(dinv + s) * __ldg(dinv + d);
}

// ------------------------------ CSR gathers --------------------------------
// Warp per node; lane l owns floats [4l, 4l+4). Plain stores, no atomics.

// z[i] = x[i]*dinv[i]^2 + sum_e w_e * x[src_e]
__global__ void k_gather_z(const float* __restrict__ h,
                           const int* __restrict__ rp, const int* __restrict__ cs,
                           const float* __restrict__ cw,
                           const float* __restrict__ dinv,
                           float* __restrict__ z, int n) {
    int t = blockIdx.x * blockDim.x + threadIdx.x;
    int i = t >> 5;
    int c = (t & 31) << 2;
    if (i >= n) return;
    float s = dinv[i];
    s *= s;
    float4 a = *(const float4*)(h + (size_t)i * 128 + c);
    float4 acc = make_float4(a.x * s, a.y * s, a.z * s, a.w * s);
    int beg = __ldg(rp + i), end = __ldg(rp + i + 1);
    for (int e = beg; e < end; e++) {
        int src = __ldg(cs + e);          // broadcast load
        float w = __ldg(cw + e);
        float4 v = *(const float4*)(h + (size_t)src * 128 + c);
        acc.x += v.x * w; acc.y += v.y * w;
        acc.z += v.z * w; acc.w += v.w * w;
    }
    *(float4*)(z + (size_t)i * 128 + c) = acc;
}

// out[i] = g1[i]*d1^2 + g2[i]*d2^2 + b2 + b3 + A1-gather(g1) + A2-gather(g2)
__global__ void k_gather_out(const float* __restrict__ g1, const float* __restrict__ g2,
                             const int* __restrict__ rp1, const int* __restrict__ cs1,
                             const float* __restrict__ cw1,
                             const int* __restrict__ rp2, const int* __restrict__ cs2,
                             const float* __restrict__ cw2,
                             const float* __restrict__ dinv1,
                             const float* __restrict__ dinv2,
                             const float* __restrict__ b2, const float* __restrict__ b3,
                             float* __restrict__ out, int n) {
    int t = blockIdx.x * blockDim.x + threadIdx.x;
    int i = t >> 5;
    int c = (t & 31) << 2;
    if (i >= n) return;
    float s1 = dinv1[i]; s1 *= s1;
    float s2 = dinv2[i]; s2 *= s2;
    float4 bb2 = *(const float4*)(b2 + c);
    float4 bb3 = *(const float4*)(b3 + c);
    float4 a1 = *(const float4*)(g1 + (size_t)i * 128 + c);
    float4 a2 = *(const float4*)(g2 + (size_t)i * 128 + c);
    float4 acc;
    acc.x = a1.x * s1 + a2.x * s2 + bb2.x + bb3.x;
    acc.y = a1.y * s1 + a2.y * s2 + bb2.y + bb3.y;
    acc.z = a1.z * s1 + a2.z * s2 + bb2.z + bb3.z;
    acc.w = a1.w * s1 + a2.w * s2 + bb2.w + bb3.w;
    int beg = __ldg(rp1 + i), end = __ldg(rp1 + i + 1);
    for (int e = beg; e < end; e++) {
        int src = __ldg(cs1 + e);
        float w = __ldg(cw1 + e);
        float4 v = *(const float4*)(g1 + (size_t)src * 128 + c);
        acc.x += v.x * w; acc.y += v.y * w;
        acc.z += v.z * w; acc.w += v.w * w;
    }
    beg = __ldg(rp2 + i); end = __ldg(rp2 + i + 1);
    for (int e = beg; e < end; e++) {
        int src = __ldg(cs2 + e);
        float w = __ldg(cw2 + e);
        float4 v = *(const float4*)(g2 + (size_t)src * 128 + c);
        acc.x += v.x * w; acc.y += v.y * w;
        acc.z += v.z * w; acc.w += v.w * w;
    }
    *(float4*)(out + (size_t)i * 128 + c) = acc;   // plain store to d_out
}

// --------------------------------- SGEMM -----------------------------------
// C[N,M] = A[N,K] @ W[K,M], BM=BN=128, BK=16, 256 thr, 8x8 microtile,
// 2-stage smem double buffering (register prefetch).
// MODE 0: C = relu(acc + bias);  MODE 3: C = acc (raw).
template<int MODE>
__global__ void __launch_bounds__(256)
k_gemm(const float* __restrict__ A, const float* __restrict__ W,
       const float* __restrict__ bias,
       float* __restrict__ C, int N, int K, int M) {
    __shared__ float As[2][16][132];
    __shared__ float Bs[2][16][132];

    const int bm = blockIdx.x * 128;
    const int bn = blockIdx.y * 128;
    const int tid = threadIdx.x;
    const int tx = tid & 15;
    const int ty = tid >> 4;
    const int aRow = tid >> 2;            // 0..63
    const int aCol = (tid & 3) << 2;      // 0,4,8,12
    const int bRow = tid >> 5;            // 0..7
    const int bCol = (tid & 31) << 2;     // 0..124

    float acc[8][8];
#pragma unroll
    for (int i = 0; i < 8; i++)
#pragma unroll
        for (int j = 0; j < 8; j++) acc[i][j] = 0.0f;

    float4 ra[2], rb[2];

    // prefetch tile kk=0
#pragma unroll
    for (int i = 0; i < 2; i++) {
        int r = bm + aRow + i * 64;
        ra[i] = make_float4(0.f, 0.f, 0.f, 0.f);
        if (r < N) ra[i] = *(const float4*)(A + (size_t)r * K + aCol);
        rb[i] = *(const float4*)(W + (size_t)(bRow + i * 8) * M + bn + bCol);
    }
#pragma unroll
    for (int i = 0; i < 2; i++) {
        As[0][aCol + 0][aRow + i * 64] = ra[i].x;
        As[0][aCol + 1][aRow + i * 64] = ra[i].y;
        As[0][aCol + 2][aRow + i * 64] = ra[i].z;
        As[0][aCol + 3][aRow + i * 64] = ra[i].w;
        *(float4*)&Bs[0][bRow + i * 8][bCol] = rb[i];
    }
    __syncthreads();

    for (int kk = 0; kk < K; kk += 16) {
        int buf = (kk >> 4) & 1;
        int kn = kk + 16;
        bool more = kn < K;
        if (more) {
#pragma unroll
            for (int i = 0; i < 2; i++) {
                int r = bm + aRow + i * 64;
                ra[i] = make_float4(0.f, 0.f, 0.f, 0.f);
                if (r < N) ra[i] = *(const float4*)(A + (size_t)r * K + kn + aCol);
                rb[i] = *(const float4*)(W + (size_t)(kn + bRow + i * 8) * M + bn + bCol);
            }
        }
#pragma unroll
        for (int k = 0; k < 16; k++) {
            float a[8], b[8];
            *(float4*)(a)     = *(const float4*)&As[buf][k][ty * 8];
            *(float4*)(a + 4) = *(const float4*)&As[buf][k][ty * 8 + 4];
            *(float4*)(b)     = *(const float4*)&Bs[buf][k][tx * 8];
            *(float4*)(b + 4) = *(const float4*)&Bs[buf][k][tx * 8 + 4];
#pragma unroll
            for (int i = 0; i < 8; i++)
#pragma unroll
                for (int j = 0; j < 8; j++)
                    acc[i][j] += a[i] * b[j];
        }
        if (more) {
            int nb = buf ^ 1;
#pragma unroll
            for (int i = 0; i < 2; i++) {
                As[nb][aCol + 0][aRow + i * 64] = ra[i].x;
                As[nb][aCol + 1][aRow + i * 64] = ra[i].y;
                As[nb][aCol + 2][aRow + i * 64] = ra[i].z;
                As[nb][aCol + 3][aRow + i * 64] = ra[i].w;
                *(float4*)&Bs[nb][bRow + i * 8][bCol] = rb[i];
            }
        }
        __syncthreads();
    }

    // epilogue
    float bb[8];
    if (MODE == 0) {
#pragma unroll
        for (int j = 0; j < 8; j++) bb[j] = bias[bn + tx * 8 + j];
    }
#pragma unroll
    for (int i = 0; i < 8; i++) {
        int row = bm + ty * 8 + i;
        if (row < N) {
            size_t off = (size_t)row * M + bn + tx * 8;
            float4 o0, o1;
            if (MODE == 0) {
                o0.x = fmaxf(acc[i][0] + bb[0], 0.f);
                o0.y = fmaxf(acc[i][1] + bb[1], 0.f);
                o0.z = fmaxf(acc[i][2] + bb[2], 0.f);
                o0.w = fmaxf(acc[i][3] + bb[3], 0.f);
                o1.x = fmaxf(acc[i][4] + bb[4], 0.f);
                o1.y = fmaxf(acc[i][5] + bb[5], 0.f);
                o1.z = fmaxf(acc[i][6] + bb[6], 0.f);
                o1.w = fmaxf(acc[i][7] + bb[7], 0.f);
            } else {
                o0 = make_float4(acc[i][0], acc[i][1], acc[i][2], acc[i][3]);
                o1 = make_float4(acc[i][4], acc[i][5], acc[i][6], acc[i][7]);
            }
            *(float4*)(C + off)     = o0;
            *(float4*)(C + off + 4) = o1;
        }
    }
}

// --------------------------------- launch ----------------------------------

extern "C" void kernel_launch(void* const* d_in, const int* in_sizes, int n_in,
                              void* d_out, int out_size) {
    const float* x   = (const float*)d_in[0];
    const void*  ei1 = d_in[1];
    const void*  ei2 = d_in[2];
    const float* W0 = (const float*)d_in[3];
    const float* b0 = (const float*)d_in[4];
    const float* W1 = (const float*)d_in[5];
    const float* b1 = (const float*)d_in[6];
    const float* W2 = (const float*)d_in[7];
    const float* b2 = (const float*)d_in[8];
    const float* W3 = (const float*)d_in[9];
    const float* b3 = (const float*)d_in[10];
    float* out = (float*)d_out;

    int N = in_sizes[0] / 128;
    int E = in_sizes[1] / 2;
    if (N > N_MAX) N = N_MAX;
    if (E > E_MAX) E = E_MAX;

    int *deg1, *deg2, *cur1, *cur2, *rp1, *rp2;
    int *es1, *ed1, *es2, *ed2, *cs1, *cs2;
    float *dinv1, *dinv2, *cw1, *cw2, *z1, *z2, *t1, *t2, *gg1, *gg2;
    cudaGetSymbolAddress((void**)&deg1,  g_deg1);
    cudaGetSymbolAddress((void**)&deg2,  g_deg2);
    cudaGetSymbolAddress((void**)&cur1,  g_cur1);
    cudaGetSymbolAddress((void**)&cur2,  g_cur2);
    cudaGetSymbolAddress((void**)&rp1,   g_rp1);
    cudaGetSymbolAddress((void**)&rp2,   g_rp2);
    cudaGetSymbolAddress((void**)&dinv1, g_dinv1);
    cudaGetSymbolAddress((void**)&dinv2, g_dinv2);
    cudaGetSymbolAddress((void**)&es1,   g_es1);
    cudaGetSymbolAddress((void**)&ed1,   g_ed1);
    cudaGetSymbolAddress((void**)&es2,   g_es2);
    cudaGetSymbolAddress((void**)&ed2,   g_ed2);
    cudaGetSymbolAddress((void**)&cs1,   g_cs1);
    cudaGetSymbolAddress((void**)&cs2,   g_cs2);
    cudaGetSymbolAddress((void**)&cw1,   g_cw1);
    cudaGetSymbolAddress((void**)&cw2,   g_cw2);
    cudaGetSymbolAddress((void**)&z1,    g_z1);
    cudaGetSymbolAddress((void**)&z2,    g_z2);
    cudaGetSymbolAddress((void**)&t1,    g_t1);
    cudaGetSymbolAddress((void**)&t2,    g_t2);
    cudaGetSymbolAddress((void**)&gg1,   g_gg1);
    cudaGetSymbolAddress((void**)&gg2,   g_gg2);

    const int T = 256;
    int gN  = (N + T - 1) / T;
    int gE  = (E + T - 1) / T;
    long long nthreads = (long long)N * 32;
    int gNW = (int)((nthreads + T - 1) / T);   // N warps (gather kernels)

    // prep: dtype detect, histogram, dinv, rowptr scan, CSR scatter
    k_detect<<<1, 32>>>(ei1, E, N);
    k_zero4<<<gN, T>>>(deg1, deg2, cur1, cur2, N);
    k_prep_edges<<<gE, T>>>(ei1, es1, ed1, deg1, E, N);
    k_prep_edges<<<gE, T>>>(ei2, es2, ed2, deg2, E, N);
    k_dinv<<<gN, T>>>(deg1, deg2, dinv1, dinv2, N);
    k_scan<<<2, 1024>>>(deg1, rp1, deg2, rp2, N);
    k_scatter<<<gE, T>>>(es1, ed1, dinv1, rp1, cur1, cs1, cw1, E);
    k_scatter<<<gE, T>>>(es2, ed2, dinv2, rp2, cur2, cs2, cw2, E);

    // z = A_hat x (CSR gather, plain stores)
    k_gather_z<<<gNW, T>>>(x, rp1, cs1, cw1, dinv1, z1, N);
    k_gather_z<<<gNW, T>>>(x, rp2, cs2, cw2, dinv2, z2, N);

    // t = relu(z W + b)
    dim3 grid1((N + 127) / 128, 2);
    k_gemm<0><<<grid1, 256>>>(z1, W0, b0, t1, N, 128, 256);
    k_gemm<0><<<grid1, 256>>>(z2, W1, b1, t2, N, 128, 256);

    // g = t W (raw)
    dim3 grid2((N + 127) / 128, 1);
    k_gemm<3><<<grid2, 256>>>(t1, W2, nullptr, gg1, N, 256, 128);
    k_gemm<3><<<grid2, 256>>>(t2, W3, nullptr, gg2, N, 256, 128);

    // out = A1 g1 + A2 g2 + b2 + b3 (CSR gather straight into d_out)
    k_gather_out<<<gNW, T>>>(gg1, gg2, rp1, cs1, cw1, rp2, cs2, cw2,
                             dinv1, dinv2, b2, b3, out, N);
}